// round 5
// baseline (speedup 1.0000x reference)
#include <cuda_runtime.h>
#include <cuda_bf16.h>
#include <cstdint>

#define N_ROWS 8192
#define N_FEAT 512
#define N_HID  256
#define H_CAT  768

// ---------------- scratch (static __device__, no allocation) ----------------
__device__ float g_t0 [N_ROWS * N_HID];
__device__ float g_h1 [N_ROWS * N_HID];
__device__ float g_t1 [N_ROWS * N_HID];
__device__ float g_cat[N_ROWS * H_CAT];
__device__ float g_o4 [N_ROWS * H_CAT];
__device__ float g_o5 [N_ROWS * H_CAT];

__device__ __forceinline__ uint32_t smem_u32(const void* p) {
    uint32_t a;
    asm("{ .reg .u64 t; cvta.to.shared.u64 t, %1; cvt.u32.u64 %0, t; }" : "=r"(a) : "l"(p));
    return a;
}

#define LDMX4(R, a) \
    asm volatile("ldmatrix.sync.aligned.m8n8.x4.shared.b16 {%0,%1,%2,%3}, [%4];" \
        : "=r"((R)[0]), "=r"((R)[1]), "=r"((R)[2]), "=r"((R)[3]) : "r"(a))
#define LDMX4T(R, a) \
    asm volatile("ldmatrix.sync.aligned.m8n8.x4.trans.shared.b16 {%0,%1,%2,%3}, [%4];" \
        : "=r"((R)[0]), "=r"((R)[1]), "=r"((R)[2]), "=r"((R)[3]) : "r"(a))
#define MMA16816(D, A4, b0, b1) \
    asm volatile("mma.sync.aligned.m16n8k16.row.col.f32.bf16.bf16.f32 " \
        "{%0,%1,%2,%3}, {%4,%5,%6,%7}, {%8,%9}, {%0,%1,%2,%3};" \
        : "+f"((D)[0]), "+f"((D)[1]), "+f"((D)[2]), "+f"((D)[3]) \
        : "r"((A4)[0]), "r"((A4)[1]), "r"((A4)[2]), "r"((A4)[3]), "r"(b0), "r"(b1))

// ---------------------------------------------------------------------------
// bf16 mma.sync GEMM: C[M,N] = op(A@B + bias). A,B,C fp32 gmem, bf16 math.
// BM=128 BN=128 BK=32, 512 threads (16 warps, 4x4), warp tile 32x32.
// Padded smem: A stride 40 bf16 (80B rows, conflict-free ldmatrix),
//              B stride 136 bf16 (272B rows, conflict-free ldmatrix).
// ---------------------------------------------------------------------------
#define AST 40
#define BST 136

__global__ __launch_bounds__(512, 1) void mma_gemm_kernel(
    const float* __restrict__ A, int lda,
    const float* __restrict__ B, int ldb,
    float* __restrict__ C, int ldc,
    const float* __restrict__ bias,
    int K, int do_relu)
{
    __shared__ __align__(16) __nv_bfloat16 sA[2][128 * AST];
    __shared__ __align__(16) __nv_bfloat16 sB[2][32 * BST];

    const int tid = threadIdx.x, lane = tid & 31, wid = tid >> 5;
    const int wm = wid & 3, wn = wid >> 2;                 // 4 x 4 warp grid
    const int m0 = blockIdx.y * 128, n0 = blockIdx.x * 128;
    const int nch = K >> 5;

    // gmem->smem mapping (per thread: 2 float4 of A, 2 float4 of B)
    const int a_c4 = tid & 7,  a_r0 = tid >> 3;   // A rows a_r0, a_r0+64 ; col quad a_c4
    const int b_c4 = tid & 31, b_k0 = tid >> 5;   // B rows b_k0, b_k0+16 ; col quad b_c4

    const uint32_t sa_u = smem_u32(&sA[0][0]);
    const uint32_t sb_u = smem_u32(&sB[0][0]);

    // ldmatrix lane addressing
    const int a_row_l = wm * 32 + (lane & 15);
    const int a_col_l = (lane >> 4) * 8;
    const int b_row_l = lane & 15;
    const int b_col_l = wn * 32 + (lane >> 4) * 8;

    float4 pa[2], pb[2];

    auto g_load = [&](int c) {
        const int kc = c << 5;
#pragma unroll
        for (int i = 0; i < 2; i++)
            pa[i] = *(const float4*)(A + (size_t)(m0 + a_r0 + 64 * i) * lda + kc + a_c4 * 4);
#pragma unroll
        for (int i = 0; i < 2; i++)
            pb[i] = *(const float4*)(B + (size_t)(kc + b_k0 + 16 * i) * ldb + n0 + b_c4 * 4);
    };
    auto s_store = [&](int buf) {
#pragma unroll
        for (int i = 0; i < 2; i++) {
            __nv_bfloat162 q0 = __float22bfloat162_rn(make_float2(pa[i].x, pa[i].y));
            __nv_bfloat162 q1 = __float22bfloat162_rn(make_float2(pa[i].z, pa[i].w));
            *(uint2*)&sA[buf][(a_r0 + 64 * i) * AST + a_c4 * 4] =
                make_uint2(*(uint32_t*)&q0, *(uint32_t*)&q1);
        }
#pragma unroll
        for (int i = 0; i < 2; i++) {
            __nv_bfloat162 q0 = __float22bfloat162_rn(make_float2(pb[i].x, pb[i].y));
            __nv_bfloat162 q1 = __float22bfloat162_rn(make_float2(pb[i].z, pb[i].w));
            *(uint2*)&sB[buf][(b_k0 + 16 * i) * BST + b_c4 * 4] =
                make_uint2(*(uint32_t*)&q0, *(uint32_t*)&q1);
        }
    };

    float acc[2][4][4];
#pragma unroll
    for (int i = 0; i < 2; i++)
#pragma unroll
        for (int j = 0; j < 4; j++)
#pragma unroll
            for (int k = 0; k < 4; k++) acc[i][j][k] = 0.0f;

    g_load(0);
    s_store(0);
    __syncthreads();

#pragma unroll 1
    for (int c = 0; c < nch; c++) {
        const int buf = c & 1;
        if (c + 1 < nch) g_load(c + 1);   // overlap gmem latency with MMAs

        const uint32_t sa = sa_u + buf * (128 * AST * 2);
        const uint32_t sb = sb_u + buf * (32 * BST * 2);

#pragma unroll
        for (int s = 0; s < 2; s++) {
            uint32_t afr[2][4];
#pragma unroll
            for (int mi = 0; mi < 2; mi++) {
                uint32_t addr = sa + (uint32_t)(((a_row_l + mi * 16) * AST + a_col_l + s * 16) * 2);
                LDMX4(afr[mi], addr);
            }
            uint32_t bfr[2][4];
#pragma unroll
            for (int j2 = 0; j2 < 2; j2++) {
                uint32_t addr = sb + (uint32_t)(((b_row_l + s * 16) * BST + b_col_l + j2 * 16) * 2);
                LDMX4T(bfr[j2], addr);
            }
#pragma unroll
            for (int mi = 0; mi < 2; mi++)
#pragma unroll
                for (int nj = 0; nj < 4; nj++)
                    MMA16816(acc[mi][nj], afr[mi], bfr[nj >> 1][(nj & 1) * 2], bfr[nj >> 1][(nj & 1) * 2 + 1]);
        }
        __syncthreads();
        if (c + 1 < nch) {
            s_store((c + 1) & 1);
            __syncthreads();
        }
    }

    // Epilogue: acc thread map: d0,d1 -> (lane/4, 2*(lane%4)); d2,d3 -> row+8
    const int er = lane >> 2, ec = (lane & 3) * 2;
#pragma unroll
    for (int mi = 0; mi < 2; mi++) {
#pragma unroll
        for (int half = 0; half < 2; half++) {
            const int r = m0 + wm * 32 + mi * 16 + er + half * 8;
            float* cp = C + (size_t)r * ldc;
#pragma unroll
            for (int nj = 0; nj < 4; nj++) {
                const int col = n0 + wn * 32 + nj * 8 + ec;
                float v0 = acc[mi][nj][half * 2 + 0];
                float v1 = acc[mi][nj][half * 2 + 1];
                if (bias) { v0 += bias[col]; v1 += bias[col + 1]; }
                if (do_relu) { v0 = fmaxf(v0, 0.0f); v1 = fmaxf(v1, 0.0f); }
                *(float2*)(cp + col) = make_float2(v0, v1);
            }
        }
    }
}

// ---------------- aux kernels ----------------
__global__ void copy_target_kernel(const float* __restrict__ tf, float* __restrict__ cat)
{
    const int idx = blockIdx.x * blockDim.x + threadIdx.x;
    const int row = idx / (N_FEAT / 4);
    const int c4  = idx % (N_FEAT / 4);
    ((float4*)(cat + (size_t)row * H_CAT + N_HID))[c4] =
        ((const float4*)(tf + (size_t)row * N_FEAT))[c4];
}

__global__ __launch_bounds__(256) void log_softmax_kernel(float* __restrict__ out)
{
    __shared__ float sred[8];
    __shared__ float s_m, s_l;
    float* p = out + (size_t)blockIdx.x * N_FEAT;
    const int tid = threadIdx.x;

    const float v0 = p[tid];
    const float v1 = p[tid + 256];

    float m = fmaxf(v0, v1);
#pragma unroll
    for (int o = 16; o; o >>= 1) m = fmaxf(m, __shfl_xor_sync(0xffffffffu, m, o));
    if ((tid & 31) == 0) sred[tid >> 5] = m;
    __syncthreads();
    if (tid == 0) {
        float mm = sred[0];
#pragma unroll
        for (int i = 1; i < 8; i++) mm = fmaxf(mm, sred[i]);
        s_m = mm;
    }
    __syncthreads();
    m = s_m;

    float s = expf(v0 - m) + expf(v1 - m);
#pragma unroll
    for (int o = 16; o; o >>= 1) s += __shfl_xor_sync(0xffffffffu, s, o);
    if ((tid & 31) == 0) sred[tid >> 5] = s;
    __syncthreads();
    if (tid == 0) {
        float ss = 0.0f;
#pragma unroll
        for (int i = 0; i < 8; i++) ss += sred[i];
        s_l = logf(ss);
    }
    __syncthreads();
    const float l = s_l;

    p[tid]       = v0 - m - l;
    p[tid + 256] = v1 - m - l;
}

// ---------------- launch ----------------
extern "C" void kernel_launch(void* const* d_in, const int* in_sizes, int n_in,
                              void* d_out, int out_size)
{
    const float* x     = (const float*)d_in[0];
    const float* tf    = (const float*)d_in[1];
    const float* adj0  = (const float*)d_in[2];
    const float* adj1  = (const float*)d_in[3];
    const float* gc1_w = (const float*)d_in[4];
    const float* gc1_b = (const float*)d_in[5];
    const float* gc2_w = (const float*)d_in[6];
    const float* gc2_b = (const float*)d_in[7];
    const float* l1w   = (const float*)d_in[8];
    const float* l1b   = (const float*)d_in[9];
    const float* l2w   = (const float*)d_in[10];
    const float* l2b   = (const float*)d_in[11];
    const float* l3w   = (const float*)d_in[12];
    const float* l3b   = (const float*)d_in[13];
    float* out = (float*)d_out;

    float *t0, *h1, *t1, *cat, *o4, *o5;
    cudaGetSymbolAddress((void**)&t0,  g_t0);
    cudaGetSymbolAddress((void**)&h1,  g_h1);
    cudaGetSymbolAddress((void**)&t1,  g_t1);
    cudaGetSymbolAddress((void**)&cat, g_cat);
    cudaGetSymbolAddress((void**)&o4,  g_o4);
    cudaGetSymbolAddress((void**)&o5,  g_o5);

    const dim3 blk(512);
    const int MT = N_ROWS / 128;   // 64

    // t0 = x @ gc1_w                       [8192,512]x[512,256]
    mma_gemm_kernel<<<dim3(N_HID / 128, MT), blk>>>(
        x, N_FEAT, gc1_w, N_HID, t0, N_HID, nullptr, N_FEAT, 0);
    // h1 = relu(adj0 @ t0 + gc1_b)         K=8192
    mma_gemm_kernel<<<dim3(N_HID / 128, MT), blk>>>(
        adj0, N_ROWS, t0, N_HID, h1, N_HID, gc1_b, N_ROWS, 1);
    // t1 = h1 @ gc2_w                      K=256
    mma_gemm_kernel<<<dim3(N_HID / 128, MT), blk>>>(
        h1, N_HID, gc2_w, N_HID, t1, N_HID, nullptr, N_HID, 0);
    // cat[:, :256] = adj1 @ t1 + gc2_b     K=8192, ldc=768
    mma_gemm_kernel<<<dim3(N_HID / 128, MT), blk>>>(
        adj1, N_ROWS, t1, N_HID, cat, H_CAT, gc2_b, N_ROWS, 0);
    // cat[:, 256:768] = target_feats
    copy_target_kernel<<<(N_ROWS * N_FEAT / 4) / 256, 256>>>(tf, cat);
    // o4 = relu(cat @ lin1_w + b)          [8192,768]x[768,768]
    mma_gemm_kernel<<<dim3(H_CAT / 128, MT), blk>>>(
        cat, H_CAT, l1w, H_CAT, o4, H_CAT, l1b, H_CAT, 1);
    // o5 = relu(o4 @ lin2_w + b)
    mma_gemm_kernel<<<dim3(H_CAT / 128, MT), blk>>>(
        o4, H_CAT, l2w, H_CAT, o5, H_CAT, l2b, H_CAT, 1);
    // out = o5 @ lin3_w + b                [8192,768]x[768,512]
    mma_gemm_kernel<<<dim3(N_FEAT / 128, MT), blk>>>(
        o5, H_CAT, l3w, N_FEAT, out, N_FEAT, l3b, H_CAT, 0);
    // log_softmax in place
    log_softmax_kernel<<<N_ROWS, 256>>>(out);
}